// round 10
// baseline (speedup 1.0000x reference)
#include <cuda_runtime.h>
#include <cuda_fp16.h>
#include <cstdint>

// Problem constants
#define NT       65536     // tokens
#define D        64        // feature dim
#define C        2048      // codes
#define M_CTA    128       // tokens per CTA (8 warps x 16)
#define NTILE    64        // codes per N-tile
#define NTILES   (C / NTILE)  // 32
#define MARGIN   1e-3f     // ambiguity margin (>= 10x worst-case 3-term fp16 error)

// Output layout (concatenated fp32, reference return order)
#define OFF_IND  4194304
#define OFF_EMB  4259840
#define OFF_CS   4390912
#define OFF_EA   4392960

#define DECAY    0.8f
#define EPSV     1e-5f

// SMEM byte offsets (k_assign)
#define XHI_OFF   0        // 128 rows x 128B (half)  = 16384
#define XLO_OFF   16384
#define B_OFF     32768    // 2 bufs x (hi 8192 | lo 8192) = 32768
#define E2_OFF    65536    // 2048 floats = 8192
#define SIDX_OFF  73728    // 128 ints = 512
#define SMEM_ASGN 74240

// Scratch (no cudaMalloc allowed)
__device__ float  g_embed_sum[C * D];
__device__ float  g_counts[C];
__device__ float  g_e2[C];
__device__ float  g_smooth[C];
__device__ __half g_ehi[C * D];   // fp16(-2*emb)
__device__ __half g_elo[C * D];   // fp16 residual
__device__ int    g_list[NT];     // ambiguous token ids
__device__ int    g_ncand;

// ---------------- PTX helpers (generic sm_80-class only) ----------------
__device__ __forceinline__ uint32_t smem_u32(const void* p) {
    uint32_t a;
    asm("{ .reg .u64 t; cvta.to.shared.u64 t, %1; cvt.u32.u64 %0, t; }" : "=r"(a) : "l"(p));
    return a;
}
__device__ __forceinline__ void cp_async16(uint32_t smem_dst, const void* gmem_src) {
    asm volatile("cp.async.cg.shared.global [%0], [%1], 16;\n" :: "r"(smem_dst), "l"(gmem_src));
}
__device__ __forceinline__ void cp_commit() {
    asm volatile("cp.async.commit_group;\n" ::: "memory");
}
__device__ __forceinline__ void ldsm4(uint32_t* r, uint32_t addr) {
    asm volatile("ldmatrix.sync.aligned.m8n8.x4.shared.b16 {%0,%1,%2,%3}, [%4];"
                 : "=r"(r[0]), "=r"(r[1]), "=r"(r[2]), "=r"(r[3]) : "r"(addr));
}
__device__ __forceinline__ void mma16816(float* d, const uint32_t* a, const uint32_t* b, const float* c) {
    asm volatile(
        "mma.sync.aligned.m16n8k16.row.col.f32.f16.f16.f32 "
        "{%0,%1,%2,%3}, {%4,%5,%6,%7}, {%8,%9}, {%10,%11,%12,%13};"
        : "=f"(d[0]), "=f"(d[1]), "=f"(d[2]), "=f"(d[3])
        : "r"(a[0]), "r"(a[1]), "r"(a[2]), "r"(a[3]),
          "r"(b[0]), "r"(b[1]),
          "f"(c[0]), "f"(c[1]), "f"(c[2]), "f"(c[3]));
}

// ---------------- K_prep: e2, split -2e into fp16 hi/lo, zero scratch ----------------
__global__ void k_prep(const float* __restrict__ emb) {
    int i = blockIdx.x * 256 + threadIdx.x;
    if (i == 0) g_ncand = 0;
    if (i < C * D) g_embed_sum[i] = 0.0f;
    if (i < C) {
        g_counts[i] = 0.0f;
        float s = 0.0f;
#pragma unroll 8
        for (int k = 0; k < D; k++) {
            float e = emb[i * D + k];
            s += e * e;
            float b = -2.0f * e;
            __half h = __float2half_rn(b);
            g_ehi[i * D + k] = h;
            g_elo[i * D + k] = __float2half_rn(b - __half2float(h));
        }
        g_e2[i] = s;
    }
}

// ---------------- K_assign: mma.sync fp16-split GEMM + argmin + ambiguity filter ----------------
// 256 threads = 8 warps x 16 tokens. A (x) hi/lo fragments live in registers.
// Mainloop is scheduled for 8-way accumulator ILP: per k-chunk, three groups of 8
// independent MMAs (Ahi*bh, Alo*bh, Ahi*bl) so dependent reuses of an accumulator
// are >= 8 issue slots apart (hides HMMA latency; throughput-bound at rt).
__global__ void __launch_bounds__(256, 2)
k_assign(const float* __restrict__ x, const float* __restrict__ emb,
         float* __restrict__ out_q, float* __restrict__ out_ind)
{
    extern __shared__ char smem[];
    const uint32_t sb = smem_u32(smem);
    const int tid = threadIdx.x;
    const int wid = tid >> 5;
    const int l   = tid & 31;
    const int tokBase = blockIdx.x * M_CTA;

    // B prefetch: tile nt into buf; 1024 x 16B chunks / 256 threads = 4 each
    auto load_b = [&](int nt, int buf) {
        uint32_t base = sb + B_OFF + (uint32_t)buf * 16384u;
#pragma unroll
        for (int i = 0; i < 4; i++) {
            int idx = tid + i * 256;           // 0..1023
            int m = idx >> 9;                  // 0 = hi, 1 = lo
            int rem = idx & 511;
            int row = rem >> 3, c = rem & 7;   // row 0..63, 16B chunk 0..7
            const __half* g = (m ? g_elo : g_ehi) + (size_t)(nt * NTILE + row) * D + c * 8;
            cp_async16(base + m * 8192u + row * 128u + (uint32_t)((c ^ (row & 7)) << 4), g);
        }
    };

    // Prologue: e2 + B0 (group0), B1 (group1)
#pragma unroll
    for (int i = 0; i < 2; i++) {
        int idx = tid + i * 256;               // 0..511 chunks of e2
        cp_async16(sb + E2_OFF + idx * 16, g_e2 + idx * 4);
    }
    load_b(0, 0);
    cp_commit();
    load_b(1, 1);
    cp_commit();

    // x tile: load 128x64 fp32, split to fp16 hi/lo, store swizzled (rows 128B)
    {
        const float4* gx = (const float4*)(x + (size_t)tokBase * D);
#pragma unroll
        for (int i = 0; i < 8; i++) {
            int idx = tid + i * 256;           // 0..2047 = 128 rows x 16 float4
            int r = idx >> 4, q = idx & 15;
            float4 v = gx[idx];
            __half h0 = __float2half_rn(v.x), h1 = __float2half_rn(v.y);
            __half h2 = __float2half_rn(v.z), h3 = __float2half_rn(v.w);
            uint32_t hi01 = (uint32_t)__half_as_ushort(h0) | ((uint32_t)__half_as_ushort(h1) << 16);
            uint32_t hi23 = (uint32_t)__half_as_ushort(h2) | ((uint32_t)__half_as_ushort(h3) << 16);
            __half l0 = __float2half_rn(v.x - __half2float(h0));
            __half l1 = __float2half_rn(v.y - __half2float(h1));
            __half l2 = __float2half_rn(v.z - __half2float(h2));
            __half l3 = __float2half_rn(v.w - __half2float(h3));
            uint32_t lo01 = (uint32_t)__half_as_ushort(l0) | ((uint32_t)__half_as_ushort(l1) << 16);
            uint32_t lo23 = (uint32_t)__half_as_ushort(l2) | ((uint32_t)__half_as_ushort(l3) << 16);
            int c = q >> 1, s = q & 1;         // 16B chunk, 8B half-sel
            uint32_t off = (uint32_t)(r * 128) + (uint32_t)((c ^ (r & 7)) << 4) + (uint32_t)(s * 8);
            *(uint2*)(smem + XHI_OFF + off) = make_uint2(hi01, hi23);
            *(uint2*)(smem + XLO_OFF + off) = make_uint2(lo01, lo23);
        }
    }
    __syncthreads();

    // A fragments (once): m16k16 per kchunk, hi and lo. ldmatrix lane map:
    // grp = l>>3: i0=(m0-7,klo) i1=(m8-15,klo) i2=(m0-7,khi) i3=(m8-15,khi)
    uint32_t Ahi[4][4], Alo[4][4];
    {
        int lr = l & 7, grp = l >> 3;
        int arow = wid * 16 + lr + (grp & 1) * 8;
#pragma unroll
        for (int kc = 0; kc < 4; kc++) {
            int chunk = 2 * kc + (grp >> 1);
            uint32_t off = (uint32_t)(arow * 128) + (uint32_t)((chunk ^ (arow & 7)) << 4);
            ldsm4(Ahi[kc], sb + XHI_OFF + off);
            ldsm4(Alo[kc], sb + XLO_OFF + off);
        }
    }

    // B ldmatrix lane map: i0=(n0-7,klo) i1=(n0-7,khi) i2=(n8-15,klo) i3=(n8-15,khi)
    const int lr = l & 7, grp = l >> 3;
    const int brow_off = lr + (grp >> 1) * 8;
    const int bsel = grp & 1;

    float bestV[2] = {3.4e38f, 3.4e38f};
    float secV[2]  = {3.4e38f, 3.4e38f};
    int   bestI[2] = {0, 0};
    const float zr[4] = {0.0f, 0.0f, 0.0f, 0.0f};

    for (int nt = 0; nt < NTILES; nt++) {
        const int buf = nt & 1;
        if (nt + 1 < NTILES) asm volatile("cp.async.wait_group 1;\n" ::: "memory");
        else                 asm volatile("cp.async.wait_group 0;\n" ::: "memory");
        __syncthreads();   // B[nt] visible to all warps

        const uint32_t bbase = sb + B_OFF + (uint32_t)buf * 16384u;
        float acc[8][4];

#pragma unroll
        for (int kc = 0; kc < 4; kc++) {
            const int chunkB = 2 * kc + bsel;
            uint32_t offp[4];
            uint32_t bh[4][4], bl[4][4];
#pragma unroll
            for (int p = 0; p < 4; p++) {
                int row = p * 16 + brow_off;
                offp[p] = (uint32_t)(row * 128) + (uint32_t)((chunkB ^ (row & 7)) << 4);
                ldsm4(bh[p], bbase + offp[p]);
            }
            // Group 1: Ahi * bh  (8 independent MMAs across all accumulators)
            if (kc == 0) {
#pragma unroll
                for (int p = 0; p < 4; p++) {
                    mma16816(acc[2 * p],     Ahi[0], bh[p] + 0, zr);
                    mma16816(acc[2 * p + 1], Ahi[0], bh[p] + 2, zr);
                }
            } else {
#pragma unroll
                for (int p = 0; p < 4; p++) {
                    mma16816(acc[2 * p],     Ahi[kc], bh[p] + 0, acc[2 * p]);
                    mma16816(acc[2 * p + 1], Ahi[kc], bh[p] + 2, acc[2 * p + 1]);
                }
            }
            // bl loads overlap group-1 MMA latency
#pragma unroll
            for (int p = 0; p < 4; p++) ldsm4(bl[p], bbase + 8192u + offp[p]);
            // Group 2: Alo * bh
#pragma unroll
            for (int p = 0; p < 4; p++) {
                mma16816(acc[2 * p],     Alo[kc], bh[p] + 0, acc[2 * p]);
                mma16816(acc[2 * p + 1], Alo[kc], bh[p] + 2, acc[2 * p + 1]);
            }
            // Group 3: Ahi * bl
#pragma unroll
            for (int p = 0; p < 4; p++) {
                mma16816(acc[2 * p],     Ahi[kc], bl[p] + 0, acc[2 * p]);
                mma16816(acc[2 * p + 1], Ahi[kc], bl[p] + 2, acc[2 * p + 1]);
            }
        }

        // Fold into per-thread (best, second). Per-thread code indices strictly increase.
#pragma unroll
        for (int n = 0; n < 8; n++) {
            int cbase = nt * NTILE + n * 8 + 2 * (l & 3);
            float2 e2p = *(const float2*)(smem + E2_OFF + (size_t)cbase * 4);
            float s[4] = { e2p.x + acc[n][0], e2p.y + acc[n][1],
                           e2p.x + acc[n][2], e2p.y + acc[n][3] };
#pragma unroll
            for (int q = 0; q < 2; q++) {      // q: column pair (idx cbase, cbase+1)
#pragma unroll
                for (int h = 0; h < 2; h++) {  // h: token half (rows +0 / +8)
                    float sv = s[h * 2 + q];
                    if (sv < bestV[h]) { secV[h] = bestV[h]; bestV[h] = sv; bestI[h] = cbase + q; }
                    else if (sv < secV[h]) { secV[h] = sv; }
                }
            }
        }

        __syncthreads();   // all warps done reading B[buf]
        if (nt + 2 < NTILES) { load_b(nt + 2, buf); cp_commit(); }
    }

    // Quad reduce (lanes sharing a row: l&~3): merge (best, idx, second) triples.
    int* sidx = (int*)(smem + SIDX_OFF);
#pragma unroll
    for (int h = 0; h < 2; h++) {
        float v = bestV[h], sec = secV[h];
        int   id = bestI[h];
#pragma unroll
        for (int off = 1; off <= 2; off <<= 1) {
            float ov = __shfl_xor_sync(0xffffffffu, v, off);
            float os = __shfl_xor_sync(0xffffffffu, sec, off);
            int   oi = __shfl_xor_sync(0xffffffffu, id, off);
            float loser;
            if (ov < v || (ov == v && oi < id)) { loser = v; v = ov; id = oi; }
            else                                { loser = ov; }
            sec = fminf(fminf(sec, os), loser);
        }
        if ((l & 3) == 0) {
            int tk = wid * 16 + (l >> 2) + h * 8;
            if (sec - v < MARGIN) {
                int p = atomicAdd(&g_ncand, 1);
                g_list[p] = tokBase + tk;
                sidx[tk] = -1;                 // defer to k_rescan
            } else {
                sidx[tk] = id;
            }
        }
    }
    __syncthreads();

    // Epilogue (unambiguous tokens only): gather quantize, indices, scatter counts/embed_sum.
    {
        int tk   = tid >> 1;
        int half = tid & 1;
        int idx  = sidx[tk];
        if (idx >= 0) {
            int gtok = tokBase + tk;
            if (half == 0) {
                atomicAdd(&g_counts[idx], 1.0f);
                out_ind[gtok] = (float)idx;
            }
            const float4* ev = (const float4*)(emb + (size_t)idx * D + half * 32);
            const float4* xv = (const float4*)(x + (size_t)gtok * D + half * 32);
            float4* qo = (float4*)(out_q + (size_t)gtok * D + half * 32);
            float* es = g_embed_sum + (size_t)idx * D + half * 32;
#pragma unroll
            for (int i = 0; i < 8; i++) {
                qo[i] = ev[i];
                float4 v = xv[i];
                atomicAdd(es + i * 4 + 0, v.x);
                atomicAdd(es + i * 4 + 1, v.y);
                atomicAdd(es + i * 4 + 2, v.z);
                atomicAdd(es + i * 4 + 3, v.w);
            }
        }
    }
}

// ---------------- K_rescan: exact fp32 argmin for ambiguous tokens ----------------
// One block per token (grid-stride). fp32 accumulation order matches the known-good
// R6 kernel exactly: even-k / odd-k partial sums, then fmaf(-2, se+so, e2).
__global__ void __launch_bounds__(256, 4)
k_rescan(const float* __restrict__ x, const float* __restrict__ emb,
         float* __restrict__ out_q, float* __restrict__ out_ind)
{
    __shared__ float xs[D];
    __shared__ float rv[8];
    __shared__ int   ri[8];
    __shared__ int   sfin;
    const int tid = threadIdx.x;
    const int n = g_ncand;

    for (int li = blockIdx.x; li < n; li += gridDim.x) {
        int tok = g_list[li];
        if (tid < D) xs[tid] = x[(size_t)tok * D + tid];
        __syncthreads();

        float best = 3.4e38f;
        int   bidx = 0;
#pragma unroll
        for (int j = 0; j < 8; j++) {
            int c = tid * 8 + j;               // per-thread codes ascending
            const float* e = emb + (size_t)c * D;
            float se = 0.0f, so = 0.0f;
#pragma unroll 16
            for (int k = 0; k < D; k += 2) {
                se = fmaf(xs[k],     e[k],     se);
                so = fmaf(xs[k + 1], e[k + 1], so);
            }
            float s = fmaf(-2.0f, se + so, g_e2[c]);
            if (s < best) { best = s; bidx = c; }
        }
        // warp reduce (tie -> lowest index)
#pragma unroll
        for (int off = 16; off; off >>= 1) {
            float ov = __shfl_xor_sync(0xffffffffu, best, off);
            int   oi = __shfl_xor_sync(0xffffffffu, bidx, off);
            if (ov < best || (ov == best && oi < bidx)) { best = ov; bidx = oi; }
        }
        if ((tid & 31) == 0) { rv[tid >> 5] = best; ri[tid >> 5] = bidx; }
        __syncthreads();
        if (tid == 0) {
            float v = rv[0]; int id = ri[0];
#pragma unroll
            for (int w = 1; w < 8; w++)
                if (rv[w] < v || (rv[w] == v && ri[w] < id)) { v = rv[w]; id = ri[w]; }
            sfin = id;
            out_ind[tok] = (float)id;
            atomicAdd(&g_counts[id], 1.0f);
        }
        __syncthreads();
        int fi = sfin;
        if (tid < D) {
            out_q[(size_t)tok * D + tid] = emb[(size_t)fi * D + tid];
            atomicAdd(&g_embed_sum[(size_t)fi * D + tid], xs[tid]);
        }
        __syncthreads();
    }
}

// ---------------- K3: cluster-size EMA + laplace smoothing (single block) ----------------
__global__ void k_cluster(const float* __restrict__ cs, float* __restrict__ out_cs) {
    __shared__ float red[32];
    __shared__ float s_tot;
    int tid = threadIdx.x;  // 1024
    float ncs[2];
    float local = 0.0f;
#pragma unroll
    for (int i = 0; i < 2; i++) {
        int c = tid + i * 1024;
        ncs[i] = cs[c] * DECAY + g_counts[c] * (1.0f - DECAY);
        out_cs[c] = ncs[i];
        local += ncs[i];
    }
#pragma unroll
    for (int o = 16; o; o >>= 1) local += __shfl_xor_sync(0xffffffffu, local, o);
    if ((tid & 31) == 0) red[tid >> 5] = local;
    __syncthreads();
    if (tid < 32) {
        float v = red[tid];
#pragma unroll
        for (int o = 16; o; o >>= 1) v += __shfl_xor_sync(0xffffffffu, v, o);
        if (tid == 0) s_tot = v;
    }
    __syncthreads();
    float tot = s_tot;
#pragma unroll
    for (int i = 0; i < 2; i++) {
        int c = tid + i * 1024;
        g_smooth[c] = (ncs[i] + EPSV) / (tot + (float)C * EPSV) * tot;
    }
}

// ---------------- K4: embed_avg EMA + renormalized embeddings ----------------
__global__ void k_embed(const float* __restrict__ ea,
                        float* __restrict__ out_emb, float* __restrict__ out_ea) {
    int i = blockIdx.x * 256 + threadIdx.x;  // over 32768 float4
    int c = i >> 4;
    float4 e = ((const float4*)ea)[i];
    float4 s = ((const float4*)g_embed_sum)[i];
    float4 na;
    na.x = e.x * DECAY + s.x * (1.0f - DECAY);
    na.y = e.y * DECAY + s.y * (1.0f - DECAY);
    na.z = e.z * DECAY + s.z * (1.0f - DECAY);
    na.w = e.w * DECAY + s.w * (1.0f - DECAY);
    ((float4*)out_ea)[i] = na;
    float sm = g_smooth[c];
    float4 ne;
    ne.x = na.x / sm; ne.y = na.y / sm; ne.z = na.z / sm; ne.w = na.w / sm;
    ((float4*)out_emb)[i] = ne;
}

// ---------------- launch ----------------
extern "C" void kernel_launch(void* const* d_in, const int* in_sizes, int n_in,
                              void* d_out, int out_size) {
    const float* x   = (const float*)d_in[0];
    const float* emb = (const float*)d_in[1];
    const float* cs  = (const float*)d_in[2];
    const float* ea  = (const float*)d_in[3];
    float* out = (float*)d_out;

    float* out_q   = out;
    float* out_ind = out + OFF_IND;
    float* out_emb = out + OFF_EMB;
    float* out_cs  = out + OFF_CS;
    float* out_ea  = out + OFF_EA;

    cudaFuncSetAttribute(k_assign, cudaFuncAttributeMaxDynamicSharedMemorySize, SMEM_ASGN);

    k_prep<<<(C * D + 255) / 256, 256>>>(emb);
    k_assign<<<NT / M_CTA, 256, SMEM_ASGN>>>(x, emb, out_q, out_ind);
    k_rescan<<<512, 256>>>(x, emb, out_q, out_ind);
    k_cluster<<<1, 1024>>>(cs, out_cs);
    k_embed<<<(C * D / 4 + 255) / 256, 256>>>(ea, out_emb, out_ea);
}

// round 14
// speedup vs baseline: 1.3399x; 1.3399x over previous
#include <cuda_runtime.h>
#include <cuda_fp16.h>
#include <cstdint>

// Problem constants
#define NT       65536     // tokens
#define D        64        // feature dim
#define C        2048      // codes
#define M_CTA    128       // tokens per CTA (8 warps x 16)
#define NTILE    64        // codes per N-tile (coarse)
#define NTILES   (C / NTILE)  // 32
#define MARGIN   0.5f      // >= 2x worst-case 1-term fp16 error (bound ~0.25)

// Output layout (concatenated fp32, reference return order)
#define OFF_IND  4194304
#define OFF_EMB  4259840
#define OFF_CS   4390912
#define OFF_EA   4392960

#define DECAY    0.8f
#define EPSV     1e-5f

// SMEM byte offsets (k_assign, coarse)
#define XHI_OFF   0        // 128 rows x 128B (half) = 16384
#define B_OFF     16384    // 2 bufs x 8192 (hi only) = 16384
#define E2_OFF    32768    // 2048 floats = 8192
#define SIDX_OFF  40960    // 128 ints = 512
#define SMEM_ASGN 41472

// Rescue kernel tiling (matches known-good R6 FFMA kernel exactly)
#define R_CT     128       // codes per smem tile
#define R_NTILES (C / R_CT)  // 16
#define R_XSTR   68        // padded x row stride (floats)
#define R_XS_BYTES   (32 * R_XSTR * 4)          // 8704
#define R_ES_BYTES   (2 * R_CT * D * 4)         // 65536
#define SMEM_RES     (R_XS_BYTES + R_ES_BYTES + 64 * 4)  // 74496

// Scratch (no cudaMalloc allowed)
__device__ float  g_embed_sum[C * D];
__device__ float  g_counts[C];
__device__ float  g_e2[C];
__device__ float  g_smooth[C];
__device__ __half g_ehi[C * D];   // fp16(-2*emb)
__device__ int    g_list[NT];     // ambiguous token ids
__device__ int    g_ncand;

// ---------------- PTX helpers (generic sm_80-class only) ----------------
__device__ __forceinline__ uint32_t smem_u32(const void* p) {
    uint32_t a;
    asm("{ .reg .u64 t; cvta.to.shared.u64 t, %1; cvt.u32.u64 %0, t; }" : "=r"(a) : "l"(p));
    return a;
}
__device__ __forceinline__ void cp_async16(uint32_t smem_dst, const void* gmem_src) {
    asm volatile("cp.async.cg.shared.global [%0], [%1], 16;\n" :: "r"(smem_dst), "l"(gmem_src));
}
__device__ __forceinline__ void cp_commit() {
    asm volatile("cp.async.commit_group;\n" ::: "memory");
}
__device__ __forceinline__ void ldsm4(uint32_t* r, uint32_t addr) {
    asm volatile("ldmatrix.sync.aligned.m8n8.x4.shared.b16 {%0,%1,%2,%3}, [%4];"
                 : "=r"(r[0]), "=r"(r[1]), "=r"(r[2]), "=r"(r[3]) : "r"(addr));
}
__device__ __forceinline__ void mma16816(float* d, const uint32_t* a, const uint32_t* b, const float* c) {
    asm volatile(
        "mma.sync.aligned.m16n8k16.row.col.f32.f16.f16.f32 "
        "{%0,%1,%2,%3}, {%4,%5,%6,%7}, {%8,%9}, {%10,%11,%12,%13};"
        : "=f"(d[0]), "=f"(d[1]), "=f"(d[2]), "=f"(d[3])
        : "r"(a[0]), "r"(a[1]), "r"(a[2]), "r"(a[3]),
          "r"(b[0]), "r"(b[1]),
          "f"(c[0]), "f"(c[1]), "f"(c[2]), "f"(c[3]));
}
__device__ __forceinline__ void fma2(unsigned long long& acc, unsigned long long a, unsigned long long b) {
    asm("fma.rn.f32x2 %0, %1, %2, %0;" : "+l"(acc) : "l"(a), "l"(b));
}
__device__ __forceinline__ void mul2(unsigned long long& acc, unsigned long long a, unsigned long long b) {
    asm("mul.rn.f32x2 %0, %1, %2;" : "=l"(acc) : "l"(a), "l"(b));
}

// ---------------- K_prep: e2, fp16(-2e), zero scratch ----------------
__global__ void k_prep(const float* __restrict__ emb) {
    int i = blockIdx.x * 256 + threadIdx.x;
    if (i == 0) g_ncand = 0;
    if (i < C * D) g_embed_sum[i] = 0.0f;
    if (i < C) {
        g_counts[i] = 0.0f;
        float s = 0.0f;
#pragma unroll 8
        for (int k = 0; k < D; k++) {
            float e = emb[i * D + k];
            s += e * e;
            g_ehi[i * D + k] = __float2half_rn(-2.0f * e);
        }
        g_e2[i] = s;
    }
}

// ---------------- K_assign: 1-term fp16 MMA coarse pass + margin filter ----------------
// 256 threads = 8 warps x 16 tokens. Per N-tile of 64 codes, per warp: 16 ldsm + 32 MMAs.
// Tokens whose (second - best) < MARGIN are deferred to the exact fp32 rescue.
__global__ void __launch_bounds__(256, 2)
k_assign(const float* __restrict__ x, const float* __restrict__ emb,
         float* __restrict__ out_q, float* __restrict__ out_ind)
{
    extern __shared__ char smem[];
    const uint32_t sb = smem_u32(smem);
    const int tid = threadIdx.x;
    const int wid = tid >> 5;
    const int l   = tid & 31;
    const int tokBase = blockIdx.x * M_CTA;

    // B prefetch (hi only): 512 x 16B chunks / 256 threads = 2 each
    auto load_b = [&](int nt, int buf) {
        uint32_t base = sb + B_OFF + (uint32_t)buf * 8192u;
#pragma unroll
        for (int i = 0; i < 2; i++) {
            int idx = tid + i * 256;           // 0..511
            int row = idx >> 3, c = idx & 7;   // row 0..63, 16B chunk 0..7
            const __half* g = g_ehi + (size_t)(nt * NTILE + row) * D + c * 8;
            cp_async16(base + row * 128u + (uint32_t)((c ^ (row & 7)) << 4), g);
        }
    };

    // Prologue: e2 + B0 (group0), B1 (group1)
#pragma unroll
    for (int i = 0; i < 2; i++) {
        int idx = tid + i * 256;               // 0..511 chunks of e2
        cp_async16(sb + E2_OFF + idx * 16, g_e2 + idx * 4);
    }
    load_b(0, 0);
    cp_commit();
    load_b(1, 1);
    cp_commit();

    // x tile: load 128x64 fp32, fp16 hi only, store swizzled (rows 128B)
    {
        const float4* gx = (const float4*)(x + (size_t)tokBase * D);
#pragma unroll
        for (int i = 0; i < 8; i++) {
            int idx = tid + i * 256;           // 0..2047 = 128 rows x 16 float4
            int r = idx >> 4, q = idx & 15;
            float4 v = gx[idx];
            uint32_t hi01 = (uint32_t)__half_as_ushort(__float2half_rn(v.x))
                          | ((uint32_t)__half_as_ushort(__float2half_rn(v.y)) << 16);
            uint32_t hi23 = (uint32_t)__half_as_ushort(__float2half_rn(v.z))
                          | ((uint32_t)__half_as_ushort(__float2half_rn(v.w)) << 16);
            int c = q >> 1, s = q & 1;         // 16B chunk, 8B half-sel
            uint32_t off = (uint32_t)(r * 128) + (uint32_t)((c ^ (r & 7)) << 4) + (uint32_t)(s * 8);
            *(uint2*)(smem + XHI_OFF + off) = make_uint2(hi01, hi23);
        }
    }
    __syncthreads();

    // A fragments (once): m16k16 per kchunk. ldmatrix lane map:
    // grp = l>>3: i0=(m0-7,klo) i1=(m8-15,klo) i2=(m0-7,khi) i3=(m8-15,khi)
    uint32_t Ahi[4][4];
    {
        int lr = l & 7, grp = l >> 3;
        int arow = wid * 16 + lr + (grp & 1) * 8;
#pragma unroll
        for (int kc = 0; kc < 4; kc++) {
            int chunk = 2 * kc + (grp >> 1);
            uint32_t off = (uint32_t)(arow * 128) + (uint32_t)((chunk ^ (arow & 7)) << 4);
            ldsm4(Ahi[kc], sb + XHI_OFF + off);
        }
    }

    // B ldmatrix lane map: i0=(n0-7,klo) i1=(n0-7,khi) i2=(n8-15,klo) i3=(n8-15,khi)
    const int lr = l & 7, grp = l >> 3;
    const int brow_off = lr + (grp >> 1) * 8;
    const int bsel = grp & 1;

    float bestV[2] = {3.4e38f, 3.4e38f};
    float secV[2]  = {3.4e38f, 3.4e38f};
    int   bestI[2] = {0, 0};
    const float zr[4] = {0.0f, 0.0f, 0.0f, 0.0f};

    for (int nt = 0; nt < NTILES; nt++) {
        const int buf = nt & 1;
        if (nt + 1 < NTILES) asm volatile("cp.async.wait_group 1;\n" ::: "memory");
        else                 asm volatile("cp.async.wait_group 0;\n" ::: "memory");
        __syncthreads();   // B[nt] visible to all warps

        const uint32_t bbase = sb + B_OFF + (uint32_t)buf * 8192u;
        float acc[8][4];

#pragma unroll
        for (int kc = 0; kc < 4; kc++) {
            const int chunkB = 2 * kc + bsel;
            uint32_t bh[4][4];
#pragma unroll
            for (int p = 0; p < 4; p++) {
                int row = p * 16 + brow_off;
                uint32_t off = (uint32_t)(row * 128) + (uint32_t)((chunkB ^ (row & 7)) << 4);
                ldsm4(bh[p], bbase + off);
            }
            // 8 independent MMAs (one per accumulator) per k-chunk
            if (kc == 0) {
#pragma unroll
                for (int p = 0; p < 4; p++) {
                    mma16816(acc[2 * p],     Ahi[0], bh[p] + 0, zr);
                    mma16816(acc[2 * p + 1], Ahi[0], bh[p] + 2, zr);
                }
            } else {
#pragma unroll
                for (int p = 0; p < 4; p++) {
                    mma16816(acc[2 * p],     Ahi[kc], bh[p] + 0, acc[2 * p]);
                    mma16816(acc[2 * p + 1], Ahi[kc], bh[p] + 2, acc[2 * p + 1]);
                }
            }
        }

        // Fold into per-thread (best, second). Per-thread code indices strictly increase.
#pragma unroll
        for (int n = 0; n < 8; n++) {
            int cbase = nt * NTILE + n * 8 + 2 * (l & 3);
            float2 e2p = *(const float2*)(smem + E2_OFF + (size_t)cbase * 4);
            float s[4] = { e2p.x + acc[n][0], e2p.y + acc[n][1],
                           e2p.x + acc[n][2], e2p.y + acc[n][3] };
#pragma unroll
            for (int q = 0; q < 2; q++) {
#pragma unroll
                for (int h = 0; h < 2; h++) {
                    float sv = s[h * 2 + q];
                    if (sv < bestV[h]) { secV[h] = bestV[h]; bestV[h] = sv; bestI[h] = cbase + q; }
                    else if (sv < secV[h]) { secV[h] = sv; }
                }
            }
        }

        __syncthreads();   // all warps done reading B[buf]
        if (nt + 2 < NTILES) { load_b(nt + 2, buf); cp_commit(); }
    }

    // Quad reduce (lanes sharing a row: l&~3): merge (best, idx, second) triples.
    int* sidx = (int*)(smem + SIDX_OFF);
#pragma unroll
    for (int h = 0; h < 2; h++) {
        float v = bestV[h], sec = secV[h];
        int   id = bestI[h];
#pragma unroll
        for (int off = 1; off <= 2; off <<= 1) {
            float ov = __shfl_xor_sync(0xffffffffu, v, off);
            float os = __shfl_xor_sync(0xffffffffu, sec, off);
            int   oi = __shfl_xor_sync(0xffffffffu, id, off);
            float loser;
            if (ov < v || (ov == v && oi < id)) { loser = v; v = ov; id = oi; }
            else                                { loser = ov; }
            sec = fminf(fminf(sec, os), loser);
        }
        if ((l & 3) == 0) {
            int tk = wid * 16 + (l >> 2) + h * 8;
            if (sec - v < MARGIN) {
                int p = atomicAdd(&g_ncand, 1);
                g_list[p] = tokBase + tk;
                sidx[tk] = -1;                 // defer to exact rescue
            } else {
                sidx[tk] = id;
            }
        }
    }
    __syncthreads();

    // Epilogue (unambiguous tokens only): gather quantize, indices, scatter counts/embed_sum.
    {
        int tk   = tid >> 1;
        int half = tid & 1;
        int idx  = sidx[tk];
        if (idx >= 0) {
            int gtok = tokBase + tk;
            if (half == 0) {
                atomicAdd(&g_counts[idx], 1.0f);
                out_ind[gtok] = (float)idx;
            }
            const float4* ev = (const float4*)(emb + (size_t)idx * D + half * 32);
            const float4* xv = (const float4*)(x + (size_t)gtok * D + half * 32);
            float4* qo = (float4*)(out_q + (size_t)gtok * D + half * 32);
            float* es = g_embed_sum + (size_t)idx * D + half * 32;
#pragma unroll
            for (int i = 0; i < 8; i++) {
                qo[i] = ev[i];
                float4 v = xv[i];
                atomicAdd(es + i * 4 + 0, v.x);
                atomicAdd(es + i * 4 + 1, v.y);
                atomicAdd(es + i * 4 + 2, v.z);
                atomicAdd(es + i * 4 + 3, v.w);
            }
        }
    }
}

// ---------------- K_rescan: exact fp32 batched rescue (R6 FFMA2 pipeline) ----------------
// Blocks process 32 gathered tokens each (grid-stride). Identical accumulation order to
// the known-good R6 kernel: packed f32x2 even/odd partial sums, fmaf(-2, lo+hi, e2),
// codes visited in ascending order, strict < tie-break, 16-lane shfl reduce.
__global__ void __launch_bounds__(128, 2)
k_rescan(const float* __restrict__ x, const float* __restrict__ emb,
         float* __restrict__ out_q, float* __restrict__ out_ind)
{
    extern __shared__ char smem[];           // same extern-shared decl as k_assign
    float* xs   = (float*)smem;                          // [32][68]
    float* es   = (float*)(smem + R_XS_BYTES);           // 2 x [128][64] swizzled
    int*   sidx = (int*)(smem + R_XS_BYTES + R_ES_BYTES); // [32]
    int*   stok = sidx + 32;                              // [32]
    const uint32_t es_b = smem_u32(es);

    const int tid = threadIdx.x;
    const int tx  = tid & 15;   // code lane
    const int ty  = tid >> 4;   // token group (0..7), 4 tokens each
    const int n   = g_ncand;

    for (int ti = blockIdx.x; ti * 32 < n; ti += gridDim.x) {
        // Gather token ids for this tile
        if (tid < 32) {
            int li = ti * 32 + tid;
            stok[tid] = (li < n) ? g_list[li] : -1;
        }
        __syncthreads();

        // Load x rows (padded layout): 512 float4 / 128 threads = 4 each
#pragma unroll
        for (int i = 0; i < 4; i++) {
            int idx = tid + i * 128;
            int r = idx >> 4, q = idx & 15;
            int tok = stok[r];
            float4 v = (tok >= 0) ? *(const float4*)(x + (size_t)tok * D + q * 4)
                                  : make_float4(0.f, 0.f, 0.f, 0.f);
            *(float4*)&xs[r * R_XSTR + q * 4] = v;
        }

        // Prefetch code tile 0 (swizzled): 2048 chunks / 128 threads = 16 each
#pragma unroll
        for (int i = 0; i < 16; i++) {
            int idx = tid + i * 128;
            int c = idx >> 4, q = idx & 15;
            cp_async16(es_b + (uint32_t)(c * D * 4) + (uint32_t)((q ^ (c & 15)) << 4),
                       emb + (size_t)c * D + q * 4);
        }
        cp_commit();

        float bestVal[4];
        int   bestIdx[4];
#pragma unroll
        for (int t = 0; t < 4; t++) { bestVal[t] = 3.4e38f; bestIdx[t] = 0; }

        for (int tile = 0; tile < R_NTILES; tile++) {
            const float* esCur = es + (tile & 1) * R_CT * D;

            if (tile + 1 < R_NTILES) {
                uint32_t nb = es_b + (uint32_t)(((tile + 1) & 1) * R_CT * D * 4);
#pragma unroll
                for (int i = 0; i < 16; i++) {
                    int idx = tid + i * 128;
                    int c = idx >> 4, q = idx & 15;
                    cp_async16(nb + (uint32_t)(c * D * 4) + (uint32_t)((q ^ (c & 15)) << 4),
                               emb + ((size_t)(tile + 1) * R_CT + c) * D + q * 4);
                }
                cp_commit();
                asm volatile("cp.async.wait_group 1;\n" ::: "memory");
            } else {
                asm volatile("cp.async.wait_group 0;\n" ::: "memory");
            }
            __syncthreads();

            unsigned long long acc[4][8];
            const float* xbase = xs + ty * 4 * R_XSTR;
            const float* ebase = esCur + tx * D;

            // k4 = 0 peeled: mul writes acc
            {
                const int swoff = (tx << 2);
                ulonglong2 ef[8];
#pragma unroll
                for (int u = 0; u < 8; u++)
                    ef[u] = *(const ulonglong2*)(ebase + u * 16 * D + swoff);
#pragma unroll
                for (int t = 0; t < 4; t++) {
                    ulonglong2 xf = *(const ulonglong2*)(xbase + t * R_XSTR);
#pragma unroll
                    for (int u = 0; u < 8; u++) {
                        mul2(acc[t][u], xf.x, ef[u].x);
                        fma2(acc[t][u], xf.y, ef[u].y);
                    }
                }
            }
#pragma unroll
            for (int k4 = 1; k4 < 16; k4++) {
                const int swoff = ((k4 ^ tx) << 2);
                ulonglong2 ef[8];
#pragma unroll
                for (int u = 0; u < 8; u++)
                    ef[u] = *(const ulonglong2*)(ebase + u * 16 * D + swoff);
#pragma unroll
                for (int t = 0; t < 4; t++) {
                    ulonglong2 xf = *(const ulonglong2*)(xbase + t * R_XSTR + k4 * 4);
#pragma unroll
                    for (int u = 0; u < 8; u++) {
                        fma2(acc[t][u], xf.x, ef[u].x);
                        fma2(acc[t][u], xf.y, ef[u].y);
                    }
                }
            }

#pragma unroll
            for (int u = 0; u < 8; u++) {
                int   ci = tile * R_CT + u * 16 + tx;
                float e2 = __ldg(&g_e2[ci]);
#pragma unroll
                for (int t = 0; t < 4; t++) {
                    float lo = __uint_as_float((unsigned)(acc[t][u] & 0xffffffffull));
                    float hi = __uint_as_float((unsigned)(acc[t][u] >> 32));
                    float s  = fmaf(-2.0f, lo + hi, e2);
                    if (s < bestVal[t]) { bestVal[t] = s; bestIdx[t] = ci; }
                }
            }
            __syncthreads();
        }

        // 16-lane argmin reduce (tie -> lowest index)
#pragma unroll
        for (int t = 0; t < 4; t++) {
            float v = bestVal[t];
            int   id = bestIdx[t];
#pragma unroll
            for (int off = 8; off >= 1; off >>= 1) {
                float ov = __shfl_xor_sync(0xffffffffu, v, off);
                int   oi = __shfl_xor_sync(0xffffffffu, id, off);
                if (ov < v || (ov == v && oi < id)) { v = ov; id = oi; }
            }
            if (tx == 0) sidx[ty * 4 + t] = id;
        }
        __syncthreads();

        // Epilogue: 4 threads per token, 16 dims each
        {
            int tk   = tid >> 2;
            int part = tid & 3;
            int tok  = stok[tk];
            if (tok >= 0) {
                int idx = sidx[tk];
                if (part == 0) {
                    atomicAdd(&g_counts[idx], 1.0f);
                    out_ind[tok] = (float)idx;
                }
                const float4* ev = (const float4*)(emb + (size_t)idx * D + part * 16);
                const float4* xv = (const float4*)(xs + tk * R_XSTR + part * 16);
                float4* qo = (float4*)(out_q + (size_t)tok * D + part * 16);
                float* esum = g_embed_sum + (size_t)idx * D + part * 16;
#pragma unroll
                for (int i = 0; i < 4; i++) {
                    qo[i] = ev[i];
                    float4 v = xv[i];
                    atomicAdd(esum + i * 4 + 0, v.x);
                    atomicAdd(esum + i * 4 + 1, v.y);
                    atomicAdd(esum + i * 4 + 2, v.z);
                    atomicAdd(esum + i * 4 + 3, v.w);
                }
            }
        }
        __syncthreads();   // smem reuse across grid-stride iterations
    }
}

// ---------------- K3: cluster-size EMA + laplace smoothing (single block) ----------------
__global__ void k_cluster(const float* __restrict__ cs, float* __restrict__ out_cs) {
    __shared__ float red[32];
    __shared__ float s_tot;
    int tid = threadIdx.x;  // 1024
    float ncs[2];
    float local = 0.0f;
#pragma unroll
    for (int i = 0; i < 2; i++) {
        int c = tid + i * 1024;
        ncs[i] = cs[c] * DECAY + g_counts[c] * (1.0f - DECAY);
        out_cs[c] = ncs[i];
        local += ncs[i];
    }
#pragma unroll
    for (int o = 16; o; o >>= 1) local += __shfl_xor_sync(0xffffffffu, local, o);
    if ((tid & 31) == 0) red[tid >> 5] = local;
    __syncthreads();
    if (tid < 32) {
        float v = red[tid];
#pragma unroll
        for (int o = 16; o; o >>= 1) v += __shfl_xor_sync(0xffffffffu, v, o);
        if (tid == 0) s_tot = v;
    }
    __syncthreads();
    float tot = s_tot;
#pragma unroll
    for (int i = 0; i < 2; i++) {
        int c = tid + i * 1024;
        g_smooth[c] = (ncs[i] + EPSV) / (tot + (float)C * EPSV) * tot;
    }
}

// ---------------- K4: embed_avg EMA + renormalized embeddings ----------------
__global__ void k_embed(const float* __restrict__ ea,
                        float* __restrict__ out_emb, float* __restrict__ out_ea) {
    int i = blockIdx.x * 256 + threadIdx.x;  // over 32768 float4
    int c = i >> 4;
    float4 e = ((const float4*)ea)[i];
    float4 s = ((const float4*)g_embed_sum)[i];
    float4 na;
    na.x = e.x * DECAY + s.x * (1.0f - DECAY);
    na.y = e.y * DECAY + s.y * (1.0f - DECAY);
    na.z = e.z * DECAY + s.z * (1.0f - DECAY);
    na.w = e.w * DECAY + s.w * (1.0f - DECAY);
    ((float4*)out_ea)[i] = na;
    float sm = g_smooth[c];
    float4 ne;
    ne.x = na.x / sm; ne.y = na.y / sm; ne.z = na.z / sm; ne.w = na.w / sm;
    ((float4*)out_emb)[i] = ne;
}

// ---------------- launch ----------------
extern "C" void kernel_launch(void* const* d_in, const int* in_sizes, int n_in,
                              void* d_out, int out_size) {
    const float* x   = (const float*)d_in[0];
    const float* emb = (const float*)d_in[1];
    const float* cs  = (const float*)d_in[2];
    const float* ea  = (const float*)d_in[3];
    float* out = (float*)d_out;

    float* out_q   = out;
    float* out_ind = out + OFF_IND;
    float* out_emb = out + OFF_EMB;
    float* out_cs  = out + OFF_CS;
    float* out_ea  = out + OFF_EA;

    cudaFuncSetAttribute(k_assign, cudaFuncAttributeMaxDynamicSharedMemorySize, SMEM_ASGN);
    cudaFuncSetAttribute(k_rescan, cudaFuncAttributeMaxDynamicSharedMemorySize, SMEM_RES);

    k_prep<<<(C * D + 255) / 256, 256>>>(emb);
    k_assign<<<NT / M_CTA, 256, SMEM_ASGN>>>(x, emb, out_q, out_ind);
    k_rescan<<<1024, 128, SMEM_RES>>>(x, emb, out_q, out_ind);
    k_cluster<<<1, 1024>>>(cs, out_cs);
    k_embed<<<(C * D / 4 + 255) / 256, 256>>>(ea, out_emb, out_ea);
}

// round 17
// speedup vs baseline: 1.6021x; 1.1956x over previous
#include <cuda_runtime.h>
#include <cuda_fp16.h>
#include <cstdint>

// Problem constants
#define NT       65536     // tokens
#define D        64        // feature dim
#define C        2048      // codes
#define M_CTA    128       // tokens per CTA (8 warps x 16)
#define NTILE    64        // codes per N-tile (coarse)
#define NTILES   (C / NTILE)  // 32
#define MARGIN   0.25f     // > 2x deterministic 1-term fp16 score-error bound (~0.1)

// Output layout (concatenated fp32, reference return order)
#define OFF_IND  4194304
#define OFF_EMB  4259840
#define OFF_CS   4390912
#define OFF_EA   4392960

#define DECAY    0.8f
#define EPSV     1e-5f

// SMEM byte offsets (k_assign, coarse)
#define XHI_OFF   0        // 128 rows x 128B (half) = 16384
#define B_OFF     16384    // 2 bufs x 8192 (hi only) = 16384
#define E2_OFF    32768    // 2048 floats = 8192
#define SIDX_OFF  40960    // 128 ints = 512
#define SMEM_ASGN 41472

// Rescue tiling (FFMA2 pipeline identical to known-good R6 kernel)
#define R_CT     128       // codes per smem sub-tile
#define R_SLICE  512       // codes per work item (4 sub-tiles)
#define R_NSLICE (C / R_SLICE)   // 4 slices per token tile
#define R_XSTR   68        // padded x row stride (floats)
#define R_XS_BYTES   (32 * R_XSTR * 4)          // 8704
#define R_ES_BYTES   (2 * R_CT * D * 4)         // 65536
#define SMEM_RES     (R_XS_BYTES + R_ES_BYTES + 64 * 4)  // 74496

// Scratch (no cudaMalloc allowed)
__device__ float  g_embed_sum[C * D];
__device__ float  g_counts[C];
__device__ float  g_e2[C];
__device__ float  g_smooth[C];
__device__ __half g_ehi[C * D];   // fp16(-2*emb)
__device__ int    g_list[NT];     // ambiguous token ids
__device__ unsigned long long g_best[NT];  // packed (ordered score, idx) per ambiguous token
__device__ int    g_ncand;

// ---------------- PTX helpers (generic sm_80-class only) ----------------
__device__ __forceinline__ uint32_t smem_u32(const void* p) {
    uint32_t a;
    asm("{ .reg .u64 t; cvta.to.shared.u64 t, %1; cvt.u32.u64 %0, t; }" : "=r"(a) : "l"(p));
    return a;
}
__device__ __forceinline__ void cp_async16(uint32_t smem_dst, const void* gmem_src) {
    asm volatile("cp.async.cg.shared.global [%0], [%1], 16;\n" :: "r"(smem_dst), "l"(gmem_src));
}
__device__ __forceinline__ void cp_commit() {
    asm volatile("cp.async.commit_group;\n" ::: "memory");
}
__device__ __forceinline__ void ldsm4(uint32_t* r, uint32_t addr) {
    asm volatile("ldmatrix.sync.aligned.m8n8.x4.shared.b16 {%0,%1,%2,%3}, [%4];"
                 : "=r"(r[0]), "=r"(r[1]), "=r"(r[2]), "=r"(r[3]) : "r"(addr));
}
__device__ __forceinline__ void mma16816(float* d, const uint32_t* a, const uint32_t* b, const float* c) {
    asm volatile(
        "mma.sync.aligned.m16n8k16.row.col.f32.f16.f16.f32 "
        "{%0,%1,%2,%3}, {%4,%5,%6,%7}, {%8,%9}, {%10,%11,%12,%13};"
        : "=f"(d[0]), "=f"(d[1]), "=f"(d[2]), "=f"(d[3])
        : "r"(a[0]), "r"(a[1]), "r"(a[2]), "r"(a[3]),
          "r"(b[0]), "r"(b[1]),
          "f"(c[0]), "f"(c[1]), "f"(c[2]), "f"(c[3]));
}
__device__ __forceinline__ void fma2(unsigned long long& acc, unsigned long long a, unsigned long long b) {
    asm("fma.rn.f32x2 %0, %1, %2, %0;" : "+l"(acc) : "l"(a), "l"(b));
}
__device__ __forceinline__ void mul2(unsigned long long& acc, unsigned long long a, unsigned long long b) {
    asm("mul.rn.f32x2 %0, %1, %2;" : "=l"(acc) : "l"(a), "l"(b));
}
// Monotone float->uint mapping: preserves fp32 < ordering on the uint domain
__device__ __forceinline__ uint32_t orderf(float v) {
    uint32_t u = __float_as_uint(v);
    return (u & 0x80000000u) ? ~u : (u | 0x80000000u);
}

// ---------------- K_prep: one 64-thread block per code ----------------
__global__ void __launch_bounds__(64)
k_prep(const float* __restrict__ emb) {
    __shared__ float ps[2];
    const int row = blockIdx.x;        // 0..C-1
    const int k   = threadIdx.x;       // 0..63
    const int i   = row * D + k;
    float e = emb[i];
    g_ehi[i] = __float2half_rn(-2.0f * e);
    g_embed_sum[i] = 0.0f;
    float s = e * e;
#pragma unroll
    for (int o = 16; o; o >>= 1) s += __shfl_xor_sync(0xffffffffu, s, o);
    if ((k & 31) == 0) ps[k >> 5] = s;
    __syncthreads();
    if (k == 0) {
        g_e2[row] = ps[0] + ps[1];
        g_counts[row] = 0.0f;
        if (row == 0) g_ncand = 0;
    }
}

// ---------------- K_assign: 1-term fp16 MMA coarse pass + margin filter ----------------
// 256 threads = 8 warps x 16 tokens. Per N-tile of 64 codes, per warp: 16 ldsm + 32 MMAs.
// Tokens whose (second - best) < MARGIN are deferred to the exact fp32 rescue.
__global__ void __launch_bounds__(256, 2)
k_assign(const float* __restrict__ x, const float* __restrict__ emb,
         float* __restrict__ out_q, float* __restrict__ out_ind)
{
    extern __shared__ char smem[];
    const uint32_t sb = smem_u32(smem);
    const int tid = threadIdx.x;
    const int wid = tid >> 5;
    const int l   = tid & 31;
    const int tokBase = blockIdx.x * M_CTA;

    // B prefetch (hi only): 512 x 16B chunks / 256 threads = 2 each
    auto load_b = [&](int nt, int buf) {
        uint32_t base = sb + B_OFF + (uint32_t)buf * 8192u;
#pragma unroll
        for (int i = 0; i < 2; i++) {
            int idx = tid + i * 256;           // 0..511
            int row = idx >> 3, c = idx & 7;   // row 0..63, 16B chunk 0..7
            const __half* g = g_ehi + (size_t)(nt * NTILE + row) * D + c * 8;
            cp_async16(base + row * 128u + (uint32_t)((c ^ (row & 7)) << 4), g);
        }
    };

    // Prologue: e2 + B0 (group0), B1 (group1)
#pragma unroll
    for (int i = 0; i < 2; i++) {
        int idx = tid + i * 256;               // 0..511 chunks of e2
        cp_async16(sb + E2_OFF + idx * 16, g_e2 + idx * 4);
    }
    load_b(0, 0);
    cp_commit();
    load_b(1, 1);
    cp_commit();

    // x tile: load 128x64 fp32, fp16 hi only, store swizzled (rows 128B)
    {
        const float4* gx = (const float4*)(x + (size_t)tokBase * D);
#pragma unroll
        for (int i = 0; i < 8; i++) {
            int idx = tid + i * 256;           // 0..2047 = 128 rows x 16 float4
            int r = idx >> 4, q = idx & 15;
            float4 v = gx[idx];
            uint32_t hi01 = (uint32_t)__half_as_ushort(__float2half_rn(v.x))
                          | ((uint32_t)__half_as_ushort(__float2half_rn(v.y)) << 16);
            uint32_t hi23 = (uint32_t)__half_as_ushort(__float2half_rn(v.z))
                          | ((uint32_t)__half_as_ushort(__float2half_rn(v.w)) << 16);
            int c = q >> 1, s = q & 1;         // 16B chunk, 8B half-sel
            uint32_t off = (uint32_t)(r * 128) + (uint32_t)((c ^ (r & 7)) << 4) + (uint32_t)(s * 8);
            *(uint2*)(smem + XHI_OFF + off) = make_uint2(hi01, hi23);
        }
    }
    __syncthreads();

    // A fragments (once): m16k16 per kchunk. ldmatrix lane map:
    // grp = l>>3: i0=(m0-7,klo) i1=(m8-15,klo) i2=(m0-7,khi) i3=(m8-15,khi)
    uint32_t Ahi[4][4];
    {
        int lr = l & 7, grp = l >> 3;
        int arow = wid * 16 + lr + (grp & 1) * 8;
#pragma unroll
        for (int kc = 0; kc < 4; kc++) {
            int chunk = 2 * kc + (grp >> 1);
            uint32_t off = (uint32_t)(arow * 128) + (uint32_t)((chunk ^ (arow & 7)) << 4);
            ldsm4(Ahi[kc], sb + XHI_OFF + off);
        }
    }

    // B ldmatrix lane map: i0=(n0-7,klo) i1=(n0-7,khi) i2=(n8-15,klo) i3=(n8-15,khi)
    const int lr = l & 7, grp = l >> 3;
    const int brow_off = lr + (grp >> 1) * 8;
    const int bsel = grp & 1;

    float bestV[2] = {3.4e38f, 3.4e38f};
    float secV[2]  = {3.4e38f, 3.4e38f};
    int   bestI[2] = {0, 0};
    const float zr[4] = {0.0f, 0.0f, 0.0f, 0.0f};

    for (int nt = 0; nt < NTILES; nt++) {
        const int buf = nt & 1;
        if (nt + 1 < NTILES) asm volatile("cp.async.wait_group 1;\n" ::: "memory");
        else                 asm volatile("cp.async.wait_group 0;\n" ::: "memory");
        __syncthreads();   // B[nt] visible to all warps

        const uint32_t bbase = sb + B_OFF + (uint32_t)buf * 8192u;
        float acc[8][4];

#pragma unroll
        for (int kc = 0; kc < 4; kc++) {
            const int chunkB = 2 * kc + bsel;
            uint32_t bh[4][4];
#pragma unroll
            for (int p = 0; p < 4; p++) {
                int row = p * 16 + brow_off;
                uint32_t off = (uint32_t)(row * 128) + (uint32_t)((chunkB ^ (row & 7)) << 4);
                ldsm4(bh[p], bbase + off);
            }
            // 8 independent MMAs (one per accumulator) per k-chunk
            if (kc == 0) {
#pragma unroll
                for (int p = 0; p < 4; p++) {
                    mma16816(acc[2 * p],     Ahi[0], bh[p] + 0, zr);
                    mma16816(acc[2 * p + 1], Ahi[0], bh[p] + 2, zr);
                }
            } else {
#pragma unroll
                for (int p = 0; p < 4; p++) {
                    mma16816(acc[2 * p],     Ahi[kc], bh[p] + 0, acc[2 * p]);
                    mma16816(acc[2 * p + 1], Ahi[kc], bh[p] + 2, acc[2 * p + 1]);
                }
            }
        }

        // Fold into per-thread (best, second). Per-thread code indices strictly increase.
#pragma unroll
        for (int n = 0; n < 8; n++) {
            int cbase = nt * NTILE + n * 8 + 2 * (l & 3);
            float2 e2p = *(const float2*)(smem + E2_OFF + (size_t)cbase * 4);
            float s[4] = { e2p.x + acc[n][0], e2p.y + acc[n][1],
                           e2p.x + acc[n][2], e2p.y + acc[n][3] };
#pragma unroll
            for (int q = 0; q < 2; q++) {
#pragma unroll
                for (int h = 0; h < 2; h++) {
                    float sv = s[h * 2 + q];
                    if (sv < bestV[h]) { secV[h] = bestV[h]; bestV[h] = sv; bestI[h] = cbase + q; }
                    else if (sv < secV[h]) { secV[h] = sv; }
                }
            }
        }

        __syncthreads();   // all warps done reading B[buf]
        if (nt + 2 < NTILES) { load_b(nt + 2, buf); cp_commit(); }
    }

    // Quad reduce (lanes sharing a row: l&~3): merge (best, idx, second) triples.
    int* sidx = (int*)(smem + SIDX_OFF);
#pragma unroll
    for (int h = 0; h < 2; h++) {
        float v = bestV[h], sec = secV[h];
        int   id = bestI[h];
#pragma unroll
        for (int off = 1; off <= 2; off <<= 1) {
            float ov = __shfl_xor_sync(0xffffffffu, v, off);
            float os = __shfl_xor_sync(0xffffffffu, sec, off);
            int   oi = __shfl_xor_sync(0xffffffffu, id, off);
            float loser;
            if (ov < v || (ov == v && oi < id)) { loser = v; v = ov; id = oi; }
            else                                { loser = ov; }
            sec = fminf(fminf(sec, os), loser);
        }
        if ((l & 3) == 0) {
            int tk = wid * 16 + (l >> 2) + h * 8;
            if (sec - v < MARGIN) {
                int tok = tokBase + tk;
                g_best[tok] = 0xFFFFFFFFFFFFFFFFull;   // init for atomicMin rescue
                int p = atomicAdd(&g_ncand, 1);
                g_list[p] = tok;
                sidx[tk] = -1;                 // defer to exact rescue
            } else {
                sidx[tk] = id;
            }
        }
    }
    __syncthreads();

    // Epilogue (unambiguous tokens only): gather quantize, indices, scatter counts/embed_sum.
    {
        int tk   = tid >> 1;
        int half = tid & 1;
        int idx  = sidx[tk];
        if (idx >= 0) {
            int gtok = tokBase + tk;
            if (half == 0) {
                atomicAdd(&g_counts[idx], 1.0f);
                out_ind[gtok] = (float)idx;
            }
            const float4* ev = (const float4*)(emb + (size_t)idx * D + half * 32);
            const float4* xv = (const float4*)(x + (size_t)gtok * D + half * 32);
            float4* qo = (float4*)(out_q + (size_t)gtok * D + half * 32);
            float* es = g_embed_sum + (size_t)idx * D + half * 32;
#pragma unroll
            for (int i = 0; i < 8; i++) {
                qo[i] = ev[i];
                float4 v = xv[i];
                atomicAdd(es + i * 4 + 0, v.x);
                atomicAdd(es + i * 4 + 1, v.y);
                atomicAdd(es + i * 4 + 2, v.z);
                atomicAdd(es + i * 4 + 3, v.w);
            }
        }
    }
}

// ---------------- K_rescan1: exact fp32 argmin, split over code slices ----------------
// Work item = (32-token tile, 512-code slice). FFMA2 accumulation order identical to the
// known-good R6 kernel. Per-token winners merged across slices with a packed 64-bit
// atomicMin key: (ordered float bits << 32) | code index -> exact fp32 ordering AND
// lowest-index tie-break.
__global__ void __launch_bounds__(128, 2)
k_rescan1(const float* __restrict__ x, const float* __restrict__ emb)
{
    extern __shared__ char smem[];
    float* xs   = (float*)smem;                            // [32][68]
    float* es   = (float*)(smem + R_XS_BYTES);             // 2 x [128][64] swizzled
    int*   stok = (int*)(smem + R_XS_BYTES + R_ES_BYTES);  // [32]
    const uint32_t es_b = smem_u32(es);

    const int tid = threadIdx.x;
    const int tx  = tid & 15;   // code lane
    const int ty  = tid >> 4;   // token group (0..7), 4 tokens each
    const int n   = g_ncand;
    const int ntiles = (n + 31) >> 5;
    const int nwork  = ntiles * R_NSLICE;

    for (int w = blockIdx.x; w < nwork; w += gridDim.x) {
        const int tile  = w >> 2;          // token tile
        const int slice = w & 3;           // code slice
        const int codeBase = slice * R_SLICE;

        if (tid < 32) {
            int li = tile * 32 + tid;
            stok[tid] = (li < n) ? g_list[li] : -1;
        }
        __syncthreads();

        // Load x rows (padded layout): 512 float4 / 128 threads = 4 each
#pragma unroll
        for (int i = 0; i < 4; i++) {
            int idx = tid + i * 128;
            int r = idx >> 4, q = idx & 15;
            int tok = stok[r];
            float4 v = (tok >= 0) ? *(const float4*)(x + (size_t)tok * D + q * 4)
                                  : make_float4(0.f, 0.f, 0.f, 0.f);
            *(float4*)&xs[r * R_XSTR + q * 4] = v;
        }

        // Prefetch code sub-tile 0 (swizzled): 2048 chunks / 128 threads = 16 each
#pragma unroll
        for (int i = 0; i < 16; i++) {
            int idx = tid + i * 128;
            int c = idx >> 4, q = idx & 15;
            cp_async16(es_b + (uint32_t)(c * D * 4) + (uint32_t)((q ^ (c & 15)) << 4),
                       emb + (size_t)(codeBase + c) * D + q * 4);
        }
        cp_commit();

        float bestVal[4];
        int   bestIdx[4];
#pragma unroll
        for (int t = 0; t < 4; t++) { bestVal[t] = 3.4e38f; bestIdx[t] = 0; }

        for (int st = 0; st < R_SLICE / R_CT; st++) {     // 4 sub-tiles of 128 codes
            const float* esCur = es + (st & 1) * R_CT * D;

            if (st + 1 < R_SLICE / R_CT) {
                uint32_t nb = es_b + (uint32_t)(((st + 1) & 1) * R_CT * D * 4);
#pragma unroll
                for (int i = 0; i < 16; i++) {
                    int idx = tid + i * 128;
                    int c = idx >> 4, q = idx & 15;
                    cp_async16(nb + (uint32_t)(c * D * 4) + (uint32_t)((q ^ (c & 15)) << 4),
                               emb + (size_t)(codeBase + (st + 1) * R_CT + c) * D + q * 4);
                }
                cp_commit();
                asm volatile("cp.async.wait_group 1;\n" ::: "memory");
            } else {
                asm volatile("cp.async.wait_group 0;\n" ::: "memory");
            }
            __syncthreads();

            unsigned long long acc[4][8];
            const float* xbase = xs + ty * 4 * R_XSTR;
            const float* ebase = esCur + tx * D;

            // k4 = 0 peeled: mul writes acc
            {
                const int swoff = (tx << 2);
                ulonglong2 ef[8];
#pragma unroll
                for (int u = 0; u < 8; u++)
                    ef[u] = *(const ulonglong2*)(ebase + u * 16 * D + swoff);
#pragma unroll
                for (int t = 0; t < 4; t++) {
                    ulonglong2 xf = *(const ulonglong2*)(xbase + t * R_XSTR);
#pragma unroll
                    for (int u = 0; u < 8; u++) {
                        mul2(acc[t][u], xf.x, ef[u].x);
                        fma2(acc[t][u], xf.y, ef[u].y);
                    }
                }
            }
#pragma unroll
            for (int k4 = 1; k4 < 16; k4++) {
                const int swoff = ((k4 ^ tx) << 2);
                ulonglong2 ef[8];
#pragma unroll
                for (int u = 0; u < 8; u++)
                    ef[u] = *(const ulonglong2*)(ebase + u * 16 * D + swoff);
#pragma unroll
                for (int t = 0; t < 4; t++) {
                    ulonglong2 xf = *(const ulonglong2*)(xbase + t * R_XSTR + k4 * 4);
#pragma unroll
                    for (int u = 0; u < 8; u++) {
                        fma2(acc[t][u], xf.x, ef[u].x);
                        fma2(acc[t][u], xf.y, ef[u].y);
                    }
                }
            }

#pragma unroll
            for (int u = 0; u < 8; u++) {
                int   ci = codeBase + st * R_CT + u * 16 + tx;
                float e2 = __ldg(&g_e2[ci]);
#pragma unroll
                for (int t = 0; t < 4; t++) {
                    float lo = __uint_as_float((unsigned)(acc[t][u] & 0xffffffffull));
                    float hi = __uint_as_float((unsigned)(acc[t][u] >> 32));
                    float s  = fmaf(-2.0f, lo + hi, e2);
                    if (s < bestVal[t]) { bestVal[t] = s; bestIdx[t] = ci; }
                }
            }
            __syncthreads();
        }

        // 16-lane argmin reduce (tie -> lowest index), then global merge via atomicMin
#pragma unroll
        for (int t = 0; t < 4; t++) {
            float v = bestVal[t];
            int   id = bestIdx[t];
#pragma unroll
            for (int off = 8; off >= 1; off >>= 1) {
                float ov = __shfl_xor_sync(0xffffffffu, v, off);
                int   oi = __shfl_xor_sync(0xffffffffu, id, off);
                if (ov < v || (ov == v && oi < id)) { v = ov; id = oi; }
            }
            if (tx == 0) {
                int tok = stok[ty * 4 + t];
                if (tok >= 0) {
                    unsigned long long key =
                        ((unsigned long long)orderf(v) << 32) | (unsigned long long)(uint32_t)id;
                    atomicMin(&g_best[tok], key);
                }
            }
        }
        __syncthreads();   // smem reuse across grid-stride iterations
    }
}

// ---------------- K_rescan2: epilogue for rescued tokens ----------------
// 4 threads per token: read winner from g_best, write index, gather quantize,
// scatter counts / embed_sum.
__global__ void __launch_bounds__(128, 4)
k_rescan2(const float* __restrict__ x, const float* __restrict__ emb,
          float* __restrict__ out_q, float* __restrict__ out_ind)
{
    const int n = g_ncand;
    for (int base = blockIdx.x * 32; base < n; base += gridDim.x * 32) {
        int li   = base + (threadIdx.x >> 2);
        int part = threadIdx.x & 3;
        if (li < n) {
            int tok = g_list[li];
            int idx = (int)(uint32_t)(g_best[tok] & 0xffffffffull);
            if (part == 0) {
                atomicAdd(&g_counts[idx], 1.0f);
                out_ind[tok] = (float)idx;
            }
            const float4* ev = (const float4*)(emb + (size_t)idx * D + part * 16);
            const float4* xv = (const float4*)(x + (size_t)tok * D + part * 16);
            float4* qo = (float4*)(out_q + (size_t)tok * D + part * 16);
            float* esum = g_embed_sum + (size_t)idx * D + part * 16;
#pragma unroll
            for (int i = 0; i < 4; i++) {
                qo[i] = ev[i];
                float4 v = xv[i];
                atomicAdd(esum + i * 4 + 0, v.x);
                atomicAdd(esum + i * 4 + 1, v.y);
                atomicAdd(esum + i * 4 + 2, v.z);
                atomicAdd(esum + i * 4 + 3, v.w);
            }
        }
    }
}

// ---------------- K3: cluster-size EMA + laplace smoothing (single block) ----------------
__global__ void k_cluster(const float* __restrict__ cs, float* __restrict__ out_cs) {
    __shared__ float red[32];
    __shared__ float s_tot;
    int tid = threadIdx.x;  // 1024
    float ncs[2];
    float local = 0.0f;
#pragma unroll
    for (int i = 0; i < 2; i++) {
        int c = tid + i * 1024;
        ncs[i] = cs[c] * DECAY + g_counts[c] * (1.0f - DECAY);
        out_cs[c] = ncs[i];
        local += ncs[i];
    }
#pragma unroll
    for (int o = 16; o; o >>= 1) local += __shfl_xor_sync(0xffffffffu, local, o);
    if ((tid & 31) == 0) red[tid >> 5] = local;
    __syncthreads();
    if (tid < 32) {
        float v = red[tid];
#pragma unroll
        for (int o = 16; o; o >>= 1) v += __shfl_xor_sync(0xffffffffu, v, o);
        if (tid == 0) s_tot = v;
    }
    __syncthreads();
    float tot = s_tot;
#pragma unroll
    for (int i = 0; i < 2; i++) {
        int c = tid + i * 1024;
        g_smooth[c] = (ncs[i] + EPSV) / (tot + (float)C * EPSV) * tot;
    }
}

// ---------------- K4: embed_avg EMA + renormalized embeddings ----------------
__global__ void k_embed(const float* __restrict__ ea,
                        float* __restrict__ out_emb, float* __restrict__ out_ea) {
    int i = blockIdx.x * 256 + threadIdx.x;  // over 32768 float4
    int c = i >> 4;
    float4 e = ((const float4*)ea)[i];
    float4 s = ((const float4*)g_embed_sum)[i];
    float4 na;
    na.x = e.x * DECAY + s.x * (1.0f - DECAY);
    na.y = e.y * DECAY + s.y * (1.0f - DECAY);
    na.z = e.z * DECAY + s.z * (1.0f - DECAY);
    na.w = e.w * DECAY + s.w * (1.0f - DECAY);
    ((float4*)out_ea)[i] = na;
    float sm = g_smooth[c];
    float4 ne;
    ne.x = na.x / sm; ne.y = na.y / sm; ne.z = na.z / sm; ne.w = na.w / sm;
    ((float4*)out_emb)[i] = ne;
}

// ---------------- launch ----------------
extern "C" void kernel_launch(void* const* d_in, const int* in_sizes, int n_in,
                              void* d_out, int out_size) {
    const float* x   = (const float*)d_in[0];
    const float* emb = (const float*)d_in[1];
    const float* cs  = (const float*)d_in[2];
    const float* ea  = (const float*)d_in[3];
    float* out = (float*)d_out;

    float* out_q   = out;
    float* out_ind = out + OFF_IND;
    float* out_emb = out + OFF_EMB;
    float* out_cs  = out + OFF_CS;
    float* out_ea  = out + OFF_EA;

    cudaFuncSetAttribute(k_assign,  cudaFuncAttributeMaxDynamicSharedMemorySize, SMEM_ASGN);
    cudaFuncSetAttribute(k_rescan1, cudaFuncAttributeMaxDynamicSharedMemorySize, SMEM_RES);

    k_prep<<<C, 64>>>(emb);
    k_assign<<<NT / M_CTA, 256, SMEM_ASGN>>>(x, emb, out_q, out_ind);
    k_rescan1<<<1184, 128, SMEM_RES>>>(x, emb);
    k_rescan2<<<512, 128>>>(x, emb, out_q, out_ind);
    k_cluster<<<1, 1024>>>(cs, out_cs);
    k_embed<<<(C * D / 4 + 255) / 256, 256>>>(ea, out_emb, out_ea);
}